// round 7
// baseline (speedup 1.0000x reference)
#include <cuda_runtime.h>
#include <cstdint>

#define NN 50000
#define EE 400000
#define DD 256
#define GG 64
#define DOUT 16

// ---------------- static scratch ----------------
__device__ float    g_S0[NN * DD];
__device__ float    g_S1[NN * DD];
__device__ uint32_t g_WtH[3][DD * DD];   // W^T split hi (tf32), [n*256+k]
__device__ uint32_t g_WtL[3][DD * DD];   // W^T split lo
__device__ int      g_degi[NN];
__device__ float    g_dinv[NN];
__device__ int      g_rowptr[NN + 1];
__device__ int      g_cursor[NN];
__device__ int      g_csr_src[EE];
__device__ float    g_csr_w[EE];
__device__ float    g_pool[GG * DD];
__device__ float    g_cnt[GG];
__device__ int      g_flags[2];

// ---------------- index dtype ----------------
__device__ __forceinline__ long long fetch_idx(const void* p, long long i, int is32) {
    if (is32) return (long long)((const int*)p)[i];
    return ((const long long*)p)[i];
}

__global__ void k_zero() {
    int i = blockIdx.x * blockDim.x + threadIdx.x;
    if (i < NN) g_degi[i] = 0;
    if (i < GG * DD) g_pool[i] = 0.f;
    if (i < GG) g_cnt[i] = 0.f;
    if (i < 2) g_flags[i] = 0;
}

__global__ void k_detect2(const unsigned* __restrict__ ei, long long ei_words,
                          const unsigned* __restrict__ bt, long long bt_words) {
    long long i = 2ll * ((long long)blockIdx.x * blockDim.x + threadIdx.x) + 1;
    unsigned v0 = (i < ei_words) ? ei[i] : 0u;
    unsigned v1 = (i < bt_words) ? bt[i] : 0u;
#pragma unroll
    for (int o = 16; o > 0; o >>= 1) {
        v0 |= __shfl_xor_sync(0xffffffffu, v0, o);
        v1 |= __shfl_xor_sync(0xffffffffu, v1, o);
    }
    if ((threadIdx.x & 31) == 0) {
        if (v0) atomicOr(&g_flags[0], 1);
        if (v1) atomicOr(&g_flags[1], 1);
    }
}

__device__ __forceinline__ void split_tf32(float x, uint32_t& hi, uint32_t& lo) {
    asm("cvt.rna.tf32.f32 %0, %1;" : "=r"(hi) : "f"(x));
    float r = x - __uint_as_float(hi);
    asm("cvt.rna.tf32.f32 %0, %1;" : "=r"(lo) : "f"(r));
}

// transpose + tf32-split all three weight matrices once
__global__ void k_prepw(const float* __restrict__ W1, const float* __restrict__ W2,
                        const float* __restrict__ W3) {
    int idx = blockIdx.x * 256 + threadIdx.x;   // k*256+n
    if (idx >= DD * DD) return;
    int k = idx >> 8, n = idx & 255;
    const float* Ws[3] = {W1, W2, W3};
#pragma unroll
    for (int l = 0; l < 3; l++) {
        float v = Ws[l][idx];
        uint32_t h, lo;
        split_tf32(v, h, lo);
        g_WtH[l][n * DD + k] = h;
        g_WtL[l][n * DD + k] = lo;
    }
}

__global__ void k_count(const void* __restrict__ ei, long long E) {
    long long e = (long long)blockIdx.x * blockDim.x + threadIdx.x;
    if (e >= E) return;
    int is32 = g_flags[0];
    long long d = fetch_idx(ei, E + e, is32);
    atomicAdd(&g_degi[d], 1);
}

__global__ void k_scan_dinv() {
    __shared__ int part[1024];
    const int CH = (NN + 1023) / 1024;
    int t = threadIdx.x;
    int beg = t * CH, end = min(beg + CH, NN);
    int s = 0;
    for (int i = beg; i < end; i++) {
        int d = g_degi[i];
        g_dinv[i] = rsqrtf((float)d + 1.0f);
        s += d;
    }
    part[t] = s;
    __syncthreads();
    for (int off = 1; off < 1024; off <<= 1) {
        int v = (t >= off) ? part[t - off] : 0;
        __syncthreads();
        part[t] += v;
        __syncthreads();
    }
    int excl = (t == 0) ? 0 : part[t - 1];
    for (int i = beg; i < end; i++) {
        g_rowptr[i] = excl;
        g_cursor[i] = excl;
        excl += g_degi[i];
    }
    if (t == 1023) g_rowptr[NN] = part[1023];
}

__global__ void k_fill(const void* __restrict__ ei, long long E) {
    long long e = (long long)blockIdx.x * blockDim.x + threadIdx.x;
    if (e >= E) return;
    int is32 = g_flags[0];
    int s = (int)fetch_idx(ei, e, is32);
    int d = (int)fetch_idx(ei, E + e, is32);
    int pos = atomicAdd(&g_cursor[d], 1);
    g_csr_src[pos] = s;
    g_csr_w[pos] = g_dinv[s] * g_dinv[d];
}

// ---------------- 3xTF32 mma.sync GEMM v4: fragment-order smem ----------------
// C[M,256] = A[M,256] @ W. Grid (391, 2); block tile 128 x 128; 8 warps
// (2m x 4n), warp tile 64x32, BK=16, double-buffered. Shared memory holds
// operands already permuted into mma fragment order -> all fragment loads are
// LDS.128 (4x fewer shared instructions than scalar layout).
//
// A frag word packing (per k8 group q, 16-row subtile s, lane=g*4+t):
//   words {0..3} = A[(s*16)+g][t], A[..+g+8][t], A[..+g][t+4], A[..+g+8][t+4]
// B frag packing (per q, slot=jj>>1, lane=g*4+t), n = jj*8+g:
//   words {0..3} = B[t][n_even], B[t+4][n_even], B[t][n_odd], B[t+4][n_odd]

__device__ __forceinline__ void mma8(float* c, const uint32_t* a, const uint32_t* b) {
    asm volatile(
        "mma.sync.aligned.m16n8k8.row.col.f32.tf32.tf32.f32 "
        "{%0,%1,%2,%3}, {%4,%5,%6,%7}, {%8,%9}, {%0,%1,%2,%3};"
        : "+f"(c[0]), "+f"(c[1]), "+f"(c[2]), "+f"(c[3])
        : "r"(a[0]), "r"(a[1]), "r"(a[2]), "r"(a[3]), "r"(b[0]), "r"(b[1]));
}

#define BKW 16
#define BUF_WORDS 8192                    // AH 2048 | AL 2048 | BH 2048 | BL 2048
#define GEMM_SMEM (2 * BUF_WORDS * 4)     // 65536 bytes

// word index helpers (within a 2048-word quarter)
__device__ __forceinline__ int aidx(int q, int s, int lane, int w) {
    return (((q << 3) + s) << 7) + (lane << 2) + w;
}
__device__ __forceinline__ int bidx(int q, int slot, int lane, int w) {
    return (((q << 3) + slot) << 7) + (lane << 2) + w;
}

__device__ __forceinline__ void stage_chunk(
    uint32_t* buf, const float* A, const uint32_t* BhiG, const uint32_t* BloG,
    int bm, int bn, int kb, int M, int tid) {
    uint32_t* AH = buf;
    uint32_t* AL = buf + 2048;
    uint32_t* BH = buf + 4096;
    uint32_t* BL = buf + 6144;
    // A slab: 128 rows x 16 k
#pragma unroll
    for (int i = 0; i < 2; i++) {
        int f = tid + i * 256;             // 0..511
        int row = f >> 2, kp = (f & 3) * 4;
        float4 v = (bm + row < M)
            ? *(const float4*)(A + (long long)(bm + row) * DD + kb + kp)
            : make_float4(0.f, 0.f, 0.f, 0.f);
        int s = row >> 4, r16 = row & 15, gg = r16 & 7, h = r16 >> 3;
#pragma unroll
        for (int e = 0; e < 4; e++) {
            float x = (&v.x)[e];
            uint32_t hi, lo;
            split_tf32(x, hi, lo);
            int k = kp + e, q = k >> 3, kk = k & 7, tt = kk & 3, kq = kk >> 2;
            int idx = aidx(q, s, gg * 4 + tt, h + 2 * kq);
            AH[idx] = hi;
            AL[idx] = lo;
        }
    }
    // B slab: 128 n x 16 k (pre-split in global, layout [n*256+k])
#pragma unroll
    for (int i = 0; i < 2; i++) {
        int f = tid + i * 256;
        int n = f >> 2, kp = (f & 3) * 4;
        const uint32_t* ph = BhiG + (long long)(bn + n) * DD + kb + kp;
        const uint32_t* pl = BloG + (long long)(bn + n) * DD + kb + kp;
        uint4 hv = *(const uint4*)ph;
        uint4 lv = *(const uint4*)pl;
        int gg = n & 7, jj = n >> 3, slot = jj >> 1, wodd = 2 * (jj & 1);
#pragma unroll
        for (int e = 0; e < 4; e++) {
            int k = kp + e, q = k >> 3, kk = k & 7, tt = kk & 3, h = kk >> 2;
            int idx = bidx(q, slot, gg * 4 + tt, h + wodd);
            BH[idx] = (&hv.x)[e];
            BL[idx] = (&lv.x)[e];
        }
    }
}

__global__ __launch_bounds__(256, 2) void k_gemm4(const float* __restrict__ A,
                                                  const uint32_t* __restrict__ BhiG,
                                                  const uint32_t* __restrict__ BloG,
                                                  float* __restrict__ C, int M) {
    extern __shared__ uint32_t sm[];
    int tid = threadIdx.x, wid = tid >> 5, lane = tid & 31;
    int g = lane >> 2, t = lane & 3;
    int wm = wid & 1, wn = wid >> 1;
    int bm = blockIdx.x * 128, bn = blockIdx.y * 128;

    float acc[4][4][4];
#pragma unroll
    for (int i = 0; i < 4; i++)
#pragma unroll
        for (int j = 0; j < 4; j++)
#pragma unroll
            for (int q = 0; q < 4; q++) acc[i][j][q] = 0.f;

    stage_chunk(sm, A, BhiG, BloG, bm, bn, 0, M, tid);
    __syncthreads();

    const int NSTEP = DD / BKW;   // 16
    for (int c = 0; c < NSTEP; c++) {
        uint32_t* cur = sm + (c & 1) * BUF_WORDS;
        uint32_t* nxt = sm + ((c + 1) & 1) * BUF_WORDS;

        uint32_t* AH = cur;
        uint32_t* AL = cur + 2048;
        uint32_t* BH = cur + 4096;
        uint32_t* BL = cur + 6144;

#pragma unroll
        for (int q = 0; q < 2; q++) {
            // B fragments for this warp: slots wn*2, wn*2+1
            uint4 bhv0 = *(const uint4*)&BH[bidx(q, wn * 2 + 0, lane, 0)];
            uint4 bhv1 = *(const uint4*)&BH[bidx(q, wn * 2 + 1, lane, 0)];
            uint4 blv0 = *(const uint4*)&BL[bidx(q, wn * 2 + 0, lane, 0)];
            uint4 blv1 = *(const uint4*)&BL[bidx(q, wn * 2 + 1, lane, 0)];
            uint32_t bh[4][2] = {{bhv0.x, bhv0.y}, {bhv0.z, bhv0.w},
                                 {bhv1.x, bhv1.y}, {bhv1.z, bhv1.w}};
            uint32_t bl[4][2] = {{blv0.x, blv0.y}, {blv0.z, blv0.w},
                                 {blv1.x, blv1.y}, {blv1.z, blv1.w}};
#pragma unroll
            for (int i = 0; i < 4; i++) {
                int s = wm * 4 + i;
                uint4 ahv = *(const uint4*)&AH[aidx(q, s, lane, 0)];
                uint4 alv = *(const uint4*)&AL[aidx(q, s, lane, 0)];
                uint32_t ah[4] = {ahv.x, ahv.y, ahv.z, ahv.w};
                uint32_t al[4] = {alv.x, alv.y, alv.z, alv.w};
#pragma unroll
                for (int j = 0; j < 4; j++) {
                    mma8(acc[i][j], ah, bh[j]);
                    mma8(acc[i][j], ah, bl[j]);
                    mma8(acc[i][j], al, bh[j]);
                }
            }
        }

        if (c + 1 < NSTEP)
            stage_chunk(nxt, A, BhiG, BloG, bm, bn, (c + 1) * BKW, M, tid);
        __syncthreads();
    }

#pragma unroll
    for (int i = 0; i < 4; i++)
#pragma unroll
        for (int j = 0; j < 4; j++) {
            int row0 = bm + wm * 64 + i * 16 + g;
            int col  = bn + wn * 32 + 8 * j + 2 * t;
            if (row0 < M) {
                float2 v = {acc[i][j][0], acc[i][j][1]};
                *(float2*)(C + (long long)row0 * DD + col) = v;
            }
            int row1 = row0 + 8;
            if (row1 < M) {
                float2 v = {acc[i][j][2], acc[i][j][3]};
                *(float2*)(C + (long long)row1 * DD + col) = v;
            }
        }
}

// ---------------- fused aggregate: self-loop + CSR gather + bias + relu --------
__global__ __launch_bounds__(256) void k_aggregate(const float* __restrict__ tmp,
                                                   float* __restrict__ out,
                                                   const float* __restrict__ bias) {
    int node = (int)(((long long)blockIdx.x * blockDim.x + threadIdx.x) >> 5);
    int lane = threadIdx.x & 31;
    if (node >= NN) return;

    float di = g_dinv[node];
    float ws = di * di;
    const float4* r = (const float4*)(tmp + (long long)node * DD);
    float4 v0 = r[lane], v1 = r[lane + 32];
    float4 a0 = {v0.x * ws, v0.y * ws, v0.z * ws, v0.w * ws};
    float4 a1 = {v1.x * ws, v1.y * ws, v1.z * ws, v1.w * ws};

    int p = g_rowptr[node], pe = g_rowptr[node + 1];
    for (; p + 4 <= pe; p += 4) {
        int s0 = g_csr_src[p],     s1 = g_csr_src[p + 1];
        int s2 = g_csr_src[p + 2], s3 = g_csr_src[p + 3];
        float w0 = g_csr_w[p],     w1 = g_csr_w[p + 1];
        float w2 = g_csr_w[p + 2], w3 = g_csr_w[p + 3];
        const float4* r0 = (const float4*)(tmp + (long long)s0 * DD);
        const float4* r1 = (const float4*)(tmp + (long long)s1 * DD);
        const float4* r2 = (const float4*)(tmp + (long long)s2 * DD);
        const float4* r3 = (const float4*)(tmp + (long long)s3 * DD);
        float4 u00 = r0[lane], u01 = r0[lane + 32];
        float4 u10 = r1[lane], u11 = r1[lane + 32];
        float4 u20 = r2[lane], u21 = r2[lane + 32];
        float4 u30 = r3[lane], u31 = r3[lane + 32];
        a0.x += w0 * u00.x; a0.y += w0 * u00.y; a0.z += w0 * u00.z; a0.w += w0 * u00.w;
        a1.x += w0 * u01.x; a1.y += w0 * u01.y; a1.z += w0 * u01.z; a1.w += w0 * u01.w;
        a0.x += w1 * u10.x; a0.y += w1 * u10.y; a0.z += w1 * u10.z; a0.w += w1 * u10.w;
        a1.x += w1 * u11.x; a1.y += w1 * u11.y; a1.z += w1 * u11.z; a1.w += w1 * u11.w;
        a0.x += w2 * u20.x; a0.y += w2 * u20.y; a0.z += w2 * u20.z; a0.w += w2 * u20.w;
        a1.x += w2 * u21.x; a1.y += w2 * u21.y; a1.z += w2 * u21.z; a1.w += w2 * u21.w;
        a0.x += w3 * u30.x; a0.y += w3 * u30.y; a0.z += w3 * u30.z; a0.w += w3 * u30.w;
        a1.x += w3 * u31.x; a1.y += w3 * u31.y; a1.z += w3 * u31.z; a1.w += w3 * u31.w;
    }
    for (; p < pe; ++p) {
        int s = g_csr_src[p];
        float w = g_csr_w[p];
        const float4* rs = (const float4*)(tmp + (long long)s * DD);
        float4 u0 = rs[lane], u1 = rs[lane + 32];
        a0.x += w * u0.x; a0.y += w * u0.y; a0.z += w * u0.z; a0.w += w * u0.w;
        a1.x += w * u1.x; a1.y += w * u1.y; a1.z += w * u1.z; a1.w += w * u1.w;
    }

    float4 b0 = ((const float4*)bias)[lane];
    float4 b1 = ((const float4*)bias)[lane + 32];
    a0.x = fmaxf(a0.x + b0.x, 0.f); a0.y = fmaxf(a0.y + b0.y, 0.f);
    a0.z = fmaxf(a0.z + b0.z, 0.f); a0.w = fmaxf(a0.w + b0.w, 0.f);
    a1.x = fmaxf(a1.x + b1.x, 0.f); a1.y = fmaxf(a1.y + b1.y, 0.f);
    a1.z = fmaxf(a1.z + b1.z, 0.f); a1.w = fmaxf(a1.w + b1.w, 0.f);

    float4* o = (float4*)(out + (long long)node * DD);
    o[lane] = a0;
    o[lane + 32] = a1;
}

// ---------------- pool (batch sorted) + fc ----------------
__global__ void k_pool2(const float* __restrict__ h, const void* __restrict__ batch) {
    int col = threadIdx.x;
    int n0 = blockIdx.x * 128;
    int n1 = min(n0 + 128, NN);
    int is32 = g_flags[1];
    int cur = (int)fetch_idx(batch, n0, is32);
    float acc = 0.f;
    int cnt = 0;
    for (int n = n0; n < n1; n++) {
        int gid = (int)fetch_idx(batch, n, is32);
        if (gid != cur) {
            atomicAdd(&g_pool[cur * DD + col], acc);
            if (col == 0) atomicAdd(&g_cnt[cur], (float)cnt);
            acc = 0.f; cnt = 0; cur = gid;
        }
        acc += h[(long long)n * DD + col];
        cnt++;
    }
    atomicAdd(&g_pool[cur * DD + col], acc);
    if (col == 0) atomicAdd(&g_cnt[cur], (float)cnt);
}

__global__ void k_fc(const float* __restrict__ Wfc, const float* __restrict__ bfc,
                     float* __restrict__ out) {
    int tt = blockIdx.x * blockDim.x + threadIdx.x;
    if (tt >= GG * DOUT) return;
    int g = tt >> 4, o = tt & 15;
    float inv = 1.0f / fmaxf(g_cnt[g], 1.0f);
    float acc = 0.f;
#pragma unroll 8
    for (int k = 0; k < DD; k++) acc += g_pool[g * DD + k] * Wfc[k * DOUT + o];
    out[tt] = acc * inv + bfc[o];
}

// ---------------- launch ----------------
extern "C" void kernel_launch(void* const* d_in, const int* in_sizes, int n_in,
                              void* d_out, int out_size) {
    const float* x     = (const float*)d_in[0];
    const void*  ei    = d_in[1];
    const void*  batch = d_in[2];
    const float* W1 = (const float*)d_in[3];  const float* b1 = (const float*)d_in[4];
    const float* W2 = (const float*)d_in[5];  const float* b2 = (const float*)d_in[6];
    const float* W3 = (const float*)d_in[7];  const float* b3 = (const float*)d_in[8];
    const float* Wfc = (const float*)d_in[9]; const float* bfc = (const float*)d_in[10];
    float* out = (float*)d_out;

    long long E = in_sizes[1] / 2;

    float *S0, *S1;
    uint32_t *WtH, *WtL;
    cudaGetSymbolAddress((void**)&S0, g_S0);
    cudaGetSymbolAddress((void**)&S1, g_S1);
    cudaGetSymbolAddress((void**)&WtH, g_WtH);
    cudaGetSymbolAddress((void**)&WtL, g_WtL);

    cudaFuncSetAttribute(k_gemm4, cudaFuncAttributeMaxDynamicSharedMemorySize,
                         GEMM_SMEM);

    dim3 gemm_grid((NN + 127) / 128, 2);
    const float* bs[3] = {b1, b2, b3};

    k_zero<<<(NN + 255) / 256, 256>>>();                                        // 1
    k_detect2<<<(int)((in_sizes[1] / 2 + 255) / 256), 256>>>(
        (const unsigned*)ei, (long long)in_sizes[1],
        (const unsigned*)batch, (long long)in_sizes[2]);                        // 2
    k_prepw<<<DD * DD / 256, 256>>>(W1, W2, W3);                                // 3
    k_gemm4<<<gemm_grid, 256, GEMM_SMEM>>>(x, WtH, WtL, S0, NN);                // 4 (profiled)
    k_count<<<(int)((E + 255) / 256), 256>>>(ei, E);                            // 5
    k_scan_dinv<<<1, 1024>>>();                                                 // 6
    k_fill<<<(int)((E + 255) / 256), 256>>>(ei, E);                             // 7
    k_aggregate<<<(NN * 32 + 255) / 256, 256>>>(S0, S1, bs[0]);                 // 8

    const float* in = S1;
    for (int l = 1; l < 3; l++) {
        k_gemm4<<<gemm_grid, 256, GEMM_SMEM>>>(in, WtH + (size_t)l * DD * DD,
                                               WtL + (size_t)l * DD * DD, S0, NN);
        k_aggregate<<<(NN * 32 + 255) / 256, 256>>>(S0, S1, bs[l]);
        in = S1;
    }

    k_pool2<<<(NN + 127) / 128, 256>>>(S1, batch);
    k_fc<<<(GG * DOUT + 255) / 256, 256>>>(Wfc, bfc, out);
}

// round 8
// speedup vs baseline: 1.8911x; 1.8911x over previous
#include <cuda_runtime.h>
#include <cstdint>

#define NN 50000
#define EE 400000
#define DD 256
#define GG 64
#define DOUT 16

// ---------------- static scratch ----------------
__device__ float g_S0[NN * DD];
__device__ float g_S1[NN * DD];
__device__ int   g_degi[NN];
__device__ float g_dinv[NN];
__device__ int   g_rowptr[NN + 1];
__device__ int   g_cursor[NN];
__device__ int   g_csr_src[EE];
__device__ float g_csr_w[EE];
__device__ float g_pool[GG * DD];
__device__ float g_cnt[GG];
__device__ int   g_flags[2];

// ---------------- index dtype ----------------
__device__ __forceinline__ long long fetch_idx(const void* p, long long i, int is32) {
    if (is32) return (long long)((const int*)p)[i];
    return ((const long long*)p)[i];
}

__global__ void k_zero() {
    int i = blockIdx.x * blockDim.x + threadIdx.x;
    if (i < NN) g_degi[i] = 0;
    if (i < GG * DD) g_pool[i] = 0.f;
    if (i < GG) g_cnt[i] = 0.f;
    if (i < 2) g_flags[i] = 0;
}

__global__ void k_detect2(const unsigned* __restrict__ ei, long long ei_words,
                          const unsigned* __restrict__ bt, long long bt_words) {
    long long i = 2ll * ((long long)blockIdx.x * blockDim.x + threadIdx.x) + 1;
    unsigned v0 = (i < ei_words) ? ei[i] : 0u;
    unsigned v1 = (i < bt_words) ? bt[i] : 0u;
#pragma unroll
    for (int o = 16; o > 0; o >>= 1) {
        v0 |= __shfl_xor_sync(0xffffffffu, v0, o);
        v1 |= __shfl_xor_sync(0xffffffffu, v1, o);
    }
    if ((threadIdx.x & 31) == 0) {
        if (v0) atomicOr(&g_flags[0], 1);
        if (v1) atomicOr(&g_flags[1], 1);
    }
}

__global__ void k_count(const void* __restrict__ ei, long long E) {
    long long e = (long long)blockIdx.x * blockDim.x + threadIdx.x;
    if (e >= E) return;
    int is32 = g_flags[0];
    long long d = fetch_idx(ei, E + e, is32);
    atomicAdd(&g_degi[d], 1);
}

__global__ void k_scan_dinv() {
    __shared__ int part[1024];
    const int CH = (NN + 1023) / 1024;
    int t = threadIdx.x;
    int beg = t * CH, end = min(beg + CH, NN);
    int s = 0;
    for (int i = beg; i < end; i++) {
        int d = g_degi[i];
        g_dinv[i] = rsqrtf((float)d + 1.0f);
        s += d;
    }
    part[t] = s;
    __syncthreads();
    for (int off = 1; off < 1024; off <<= 1) {
        int v = (t >= off) ? part[t - off] : 0;
        __syncthreads();
        part[t] += v;
        __syncthreads();
    }
    int excl = (t == 0) ? 0 : part[t - 1];
    for (int i = beg; i < end; i++) {
        g_rowptr[i] = excl;
        g_cursor[i] = excl;
        excl += g_degi[i];
    }
    if (t == 1023) g_rowptr[NN] = part[1023];
}

__global__ void k_fill(const void* __restrict__ ei, long long E) {
    long long e = (long long)blockIdx.x * blockDim.x + threadIdx.x;
    if (e >= E) return;
    int is32 = g_flags[0];
    int s = (int)fetch_idx(ei, e, is32);
    int d = (int)fetch_idx(ei, E + e, is32);
    int pos = atomicAdd(&g_cursor[d], 1);
    g_csr_src[pos] = s;
    g_csr_w[pos] = g_dinv[s] * g_dinv[d];
}

// ---------------- 3xTF32 tensor-core GEMM v5 (reordered MMA issue) -------------
// C[M,256] = A[M,256] @ B[256,256]. Block tile 128x128 (grid 391 x 2),
// 8 warps (2m x 4n), warp tile 64x32, BK=8, double-buffered smem,
// operands pre-split to tf32 hi/lo at staging.
// Inner loop: B frags once; A frags for 2 m-subtiles; then all hh, all hl,
// all lh MMAs -> dependent MMAs on the same acc are 8 apart, not adjacent.
__device__ __forceinline__ void split_tf32(float x, uint32_t& hi, uint32_t& lo) {
    asm("cvt.rna.tf32.f32 %0, %1;" : "=r"(hi) : "f"(x));
    float r = x - __uint_as_float(hi);
    asm("cvt.rna.tf32.f32 %0, %1;" : "=r"(lo) : "f"(r));
}

__device__ __forceinline__ void mma8(float* c, const uint32_t* a, const uint32_t* b) {
    asm volatile(
        "mma.sync.aligned.m16n8k8.row.col.f32.tf32.tf32.f32 "
        "{%0,%1,%2,%3}, {%4,%5,%6,%7}, {%8,%9}, {%0,%1,%2,%3};"
        : "+f"(c[0]), "+f"(c[1]), "+f"(c[2]), "+f"(c[3])
        : "r"(a[0]), "r"(a[1]), "r"(a[2]), "r"(a[3]), "r"(b[0]), "r"(b[1]));
}

#define APAD 12    // (12g+t)%32 distinct across a warp
#define BPAD 136   // 136%32==8 -> (8t+g)%32 distinct
#define A_WORDS (2 * 2 * 128 * APAD)           // 6144
#define B_WORDS (2 * 2 * 8 * BPAD)             // 4352
#define GEMM_SMEM ((A_WORDS + B_WORDS) * 4)    // 41984 bytes

#define AS(b, h, r, k) sA[((((b) * 2 + (h)) * 128 + (r)) * APAD) + (k)]
#define BS(b, h, k, n) sB[((((b) * 2 + (h)) * 8 + (k)) * BPAD) + (n)]

__global__ __launch_bounds__(256, 2) void k_gemm5(const float* __restrict__ A,
                                                  const float* __restrict__ B,
                                                  float* __restrict__ C, int M) {
    extern __shared__ uint32_t smem_dyn[];
    uint32_t* sA = smem_dyn;
    uint32_t* sB = smem_dyn + A_WORDS;

    int tid = threadIdx.x, wid = tid >> 5, lane = tid & 31;
    int g = lane >> 2, t = lane & 3;
    int wm = wid & 1, wn = wid >> 1;       // 2(m) x 4(n); warp tile 64x32
    int bm = blockIdx.x * 128;
    int bn = blockIdx.y * 128;

    int a_row = tid >> 1;
    int a_kk  = (tid & 1) * 4;
    int b_k   = tid >> 5;
    int b_n   = (tid & 31) * 4;

    long long a_base = (long long)(bm + a_row) * DD + a_kk;
    bool a_ok = (bm + a_row) < M;
    const float4 z4 = make_float4(0.f, 0.f, 0.f, 0.f);

    float acc[4][4][4];
#pragma unroll
    for (int i = 0; i < 4; i++)
#pragma unroll
        for (int j = 0; j < 4; j++)
#pragma unroll
            for (int q = 0; q < 4; q++) acc[i][j][q] = 0.f;

    // prologue: stage slab 0
    {
        float4 pa = a_ok ? *(const float4*)(A + a_base) : z4;
        float4 pb = *(const float4*)(B + (long long)b_k * DD + bn + b_n);
        uint4 h, l;
        split_tf32(pa.x, h.x, l.x); split_tf32(pa.y, h.y, l.y);
        split_tf32(pa.z, h.z, l.z); split_tf32(pa.w, h.w, l.w);
        *(uint4*)&AS(0, 0, a_row, a_kk) = h;
        *(uint4*)&AS(0, 1, a_row, a_kk) = l;
        split_tf32(pb.x, h.x, l.x); split_tf32(pb.y, h.y, l.y);
        split_tf32(pb.z, h.z, l.z); split_tf32(pb.w, h.w, l.w);
        *(uint4*)&BS(0, 0, b_k, b_n) = h;
        *(uint4*)&BS(0, 1, b_k, b_n) = l;
    }
    __syncthreads();

    for (int k0 = 0; k0 < DD / 8; k0++) {
        int cur = k0 & 1, nxt = cur ^ 1;
        bool more = (k0 + 1) < DD / 8;

        float4 pa = z4, pb = z4;
        if (more) {
            int kb = (k0 + 1) * 8;
            pa = a_ok ? *(const float4*)(A + a_base + kb) : z4;
            pb = *(const float4*)(B + (long long)(kb + b_k) * DD + bn + b_n);
        }

        uint32_t bh[4][2], bl[4][2];
#pragma unroll
        for (int j = 0; j < 4; j++) {
            int n = wn * 32 + 8 * j + g;
            bh[j][0] = BS(cur, 0, t, n);     bh[j][1] = BS(cur, 0, t + 4, n);
            bl[j][0] = BS(cur, 1, t, n);     bl[j][1] = BS(cur, 1, t + 4, n);
        }
#pragma unroll
        for (int half = 0; half < 2; half++) {
            uint32_t ah[2][4], al[2][4];
#pragma unroll
            for (int ii = 0; ii < 2; ii++) {
                int r = wm * 64 + (half * 2 + ii) * 16;
                ah[ii][0] = AS(cur, 0, r + g, t);      ah[ii][1] = AS(cur, 0, r + g + 8, t);
                ah[ii][2] = AS(cur, 0, r + g, t + 4);  ah[ii][3] = AS(cur, 0, r + g + 8, t + 4);
                al[ii][0] = AS(cur, 1, r + g, t);      al[ii][1] = AS(cur, 1, r + g + 8, t);
                al[ii][2] = AS(cur, 1, r + g, t + 4);  al[ii][3] = AS(cur, 1, r + g + 8, t + 4);
            }
            // all hh (8), then all hl (8), then all lh (8):
            // dependent MMAs on the same acc are 8 issues apart.
#pragma unroll
            for (int ii = 0; ii < 2; ii++)
#pragma unroll
                for (int j = 0; j < 4; j++) mma8(acc[half * 2 + ii][j], ah[ii], bh[j]);
#pragma unroll
            for (int ii = 0; ii < 2; ii++)
#pragma unroll
                for (int j = 0; j < 4; j++) mma8(acc[half * 2 + ii][j], ah[ii], bl[j]);
#pragma unroll
            for (int ii = 0; ii < 2; ii++)
#pragma unroll
                for (int j = 0; j < 4; j++) mma8(acc[half * 2 + ii][j], al[ii], bh[j]);
        }

        if (more) {
            uint4 h, l;
            split_tf32(pa.x, h.x, l.x); split_tf32(pa.y, h.y, l.y);
            split_tf32(pa.z, h.z, l.z); split_tf32(pa.w, h.w, l.w);
            *(uint4*)&AS(nxt, 0, a_row, a_kk) = h;
            *(uint4*)&AS(nxt, 1, a_row, a_kk) = l;
            split_tf32(pb.x, h.x, l.x); split_tf32(pb.y, h.y, l.y);
            split_tf32(pb.z, h.z, l.z); split_tf32(pb.w, h.w, l.w);
            *(uint4*)&BS(nxt, 0, b_k, b_n) = h;
            *(uint4*)&BS(nxt, 1, b_k, b_n) = l;
        }
        __syncthreads();
    }

#pragma unroll
    for (int i = 0; i < 4; i++)
#pragma unroll
        for (int j = 0; j < 4; j++) {
            int row0 = bm + wm * 64 + i * 16 + g;
            int col  = bn + wn * 32 + 8 * j + 2 * t;
            if (row0 < M) {
                float2 v = {acc[i][j][0], acc[i][j][1]};
                *(float2*)(C + (long long)row0 * DD + col) = v;
            }
            int row1 = row0 + 8;
            if (row1 < M) {
                float2 v = {acc[i][j][2], acc[i][j][3]};
                *(float2*)(C + (long long)row1 * DD + col) = v;
            }
        }
}

// ---------------- fused aggregate: self-loop + CSR gather + bias + relu --------
__global__ __launch_bounds__(256) void k_aggregate(const float* __restrict__ tmp,
                                                   float* __restrict__ out,
                                                   const float* __restrict__ bias) {
    int node = (int)(((long long)blockIdx.x * blockDim.x + threadIdx.x) >> 5);
    int lane = threadIdx.x & 31;
    if (node >= NN) return;

    float di = g_dinv[node];
    float ws = di * di;
    const float4* r = (const float4*)(tmp + (long long)node * DD);
    float4 v0 = r[lane], v1 = r[lane + 32];
    float4 a0 = {v0.x * ws, v0.y * ws, v0.z * ws, v0.w * ws};
    float4 a1 = {v1.x * ws, v1.y * ws, v1.z * ws, v1.w * ws};

    int p = g_rowptr[node], pe = g_rowptr[node + 1];
    for (; p + 2 <= pe; p += 2) {
        int s0 = g_csr_src[p], s1 = g_csr_src[p + 1];
        float w0 = g_csr_w[p], w1 = g_csr_w[p + 1];
        const float4* r0 = (const float4*)(tmp + (long long)s0 * DD);
        const float4* r1 = (const float4*)(tmp + (long long)s1 * DD);
        float4 u00 = r0[lane], u01 = r0[lane + 32];
        float4 u10 = r1[lane], u11 = r1[lane + 32];
        a0.x += w0 * u00.x; a0.y += w0 * u00.y; a0.z += w0 * u00.z; a0.w += w0 * u00.w;
        a1.x += w0 * u01.x; a1.y += w0 * u01.y; a1.z += w0 * u01.z; a1.w += w0 * u01.w;
        a0.x += w1 * u10.x; a0.y += w1 * u10.y; a0.z += w1 * u10.z; a0.w += w1 * u10.w;
        a1.x += w1 * u11.x; a1.y += w1 * u11.y; a1.z += w1 * u11.z; a1.w += w1 * u11.w;
    }
    if (p < pe) {
        int s = g_csr_src[p];
        float w = g_csr_w[p];
        const float4* rs = (const float4*)(tmp + (long long)s * DD);
        float4 u0 = rs[lane], u1 = rs[lane + 32];
        a0.x += w * u0.x; a0.y += w * u0.y; a0.z += w * u0.z; a0.w += w * u0.w;
        a1.x += w * u1.x; a1.y += w * u1.y; a1.z += w * u1.z; a1.w += w * u1.w;
    }

    float4 b0 = ((const float4*)bias)[lane];
    float4 b1 = ((const float4*)bias)[lane + 32];
    a0.x = fmaxf(a0.x + b0.x, 0.f); a0.y = fmaxf(a0.y + b0.y, 0.f);
    a0.z = fmaxf(a0.z + b0.z, 0.f); a0.w = fmaxf(a0.w + b0.w, 0.f);
    a1.x = fmaxf(a1.x + b1.x, 0.f); a1.y = fmaxf(a1.y + b1.y, 0.f);
    a1.z = fmaxf(a1.z + b1.z, 0.f); a1.w = fmaxf(a1.w + b1.w, 0.f);

    float4* o = (float4*)(out + (long long)node * DD);
    o[lane] = a0;
    o[lane + 32] = a1;
}

// ---------------- pool (batch sorted) + fc ----------------
__global__ void k_pool2(const float* __restrict__ h, const void* __restrict__ batch) {
    int col = threadIdx.x;
    int n0 = blockIdx.x * 128;
    int n1 = min(n0 + 128, NN);
    int is32 = g_flags[1];
    int cur = (int)fetch_idx(batch, n0, is32);
    float acc = 0.f;
    int cnt = 0;
    for (int n = n0; n < n1; n++) {
        int gid = (int)fetch_idx(batch, n, is32);
        if (gid != cur) {
            atomicAdd(&g_pool[cur * DD + col], acc);
            if (col == 0) atomicAdd(&g_cnt[cur], (float)cnt);
            acc = 0.f; cnt = 0; cur = gid;
        }
        acc += h[(long long)n * DD + col];
        cnt++;
    }
    atomicAdd(&g_pool[cur * DD + col], acc);
    if (col == 0) atomicAdd(&g_cnt[cur], (float)cnt);
}

__global__ void k_fc(const float* __restrict__ Wfc, const float* __restrict__ bfc,
                     float* __restrict__ out) {
    int tt = blockIdx.x * blockDim.x + threadIdx.x;
    if (tt >= GG * DOUT) return;
    int g = tt >> 4, o = tt & 15;
    float inv = 1.0f / fmaxf(g_cnt[g], 1.0f);
    float acc = 0.f;
#pragma unroll 8
    for (int k = 0; k < DD; k++) acc += g_pool[g * DD + k] * Wfc[k * DOUT + o];
    out[tt] = acc * inv + bfc[o];
}

// ---------------- launch ----------------
extern "C" void kernel_launch(void* const* d_in, const int* in_sizes, int n_in,
                              void* d_out, int out_size) {
    const float* x     = (const float*)d_in[0];
    const void*  ei    = d_in[1];
    const void*  batch = d_in[2];
    const float* W1 = (const float*)d_in[3];  const float* b1 = (const float*)d_in[4];
    const float* W2 = (const float*)d_in[5];  const float* b2 = (const float*)d_in[6];
    const float* W3 = (const float*)d_in[7];  const float* b3 = (const float*)d_in[8];
    const float* Wfc = (const float*)d_in[9]; const float* bfc = (const float*)d_in[10];
    float* out = (float*)d_out;

    long long E = in_sizes[1] / 2;

    float *S0, *S1;
    cudaGetSymbolAddress((void**)&S0, g_S0);
    cudaGetSymbolAddress((void**)&S1, g_S1);

    cudaFuncSetAttribute(k_gemm5, cudaFuncAttributeMaxDynamicSharedMemorySize,
                         GEMM_SMEM);

    dim3 gemm_grid((NN + 127) / 128, 2);
    const float* bs[3] = {b1, b2, b3};

    // launch order: GEMM is launch #4 -> gets the ncu -s window
    k_zero<<<(NN + 255) / 256, 256>>>();                                       // 1
    k_detect2<<<(int)((in_sizes[1] / 2 + 255) / 256), 256>>>(
        (const unsigned*)ei, (long long)in_sizes[1],
        (const unsigned*)batch, (long long)in_sizes[2]);                       // 2
    k_count<<<(int)((E + 255) / 256), 256>>>(ei, E);                           // 3
    k_gemm5<<<gemm_grid, 256, GEMM_SMEM>>>(x, W1, S0, NN);                     // 4 (profiled)
    k_scan_dinv<<<1, 1024>>>();                                                // 5
    k_fill<<<(int)((E + 255) / 256), 256>>>(ei, E);                            // 6
    k_aggregate<<<(NN * 32 + 255) / 256, 256>>>(S0, S1, bs[0]);                // 7

    const float* in = S1;
    const float* Ws23[2] = {W2, W3};
    for (int l = 0; l < 2; l++) {
        k_gemm5<<<gemm_grid, 256, GEMM_SMEM>>>(in, Ws23[l], S0, NN);
        k_aggregate<<<(NN * 32 + 255) / 256, 256>>>(S0, S1, bs[l + 1]);
        in = S1;
    }

    k_pool2<<<(NN + 127) / 128, 256>>>(S1, batch);
    k_fc<<<(GG * DOUT + 255) / 256, 256>>>(Wfc, bfc, out);
}

// round 9
// speedup vs baseline: 2.4335x; 1.2868x over previous
#include <cuda_runtime.h>
#include <cstdint>

#define NN 50000
#define EE 400000
#define DD 256
#define GG 64
#define DOUT 16

// ---------------- static scratch ----------------
__device__ float    g_S0[NN * DD];
__device__ float    g_S1[NN * DD];
__device__ uint32_t g_WpH[3][128 * DD];   // W packed bf16-hi pairs: [k/2][n]
__device__ uint32_t g_WpL[3][128 * DD];   // W packed bf16-lo pairs
__device__ int      g_degi[NN];
__device__ float    g_dinv[NN];
__device__ int      g_rowptr[NN + 1];
__device__ int      g_cursor[NN];
__device__ int      g_csr_src[EE];
__device__ float    g_csr_w[EE];
__device__ float    g_pool[GG * DD];
__device__ float    g_cnt[GG];
__device__ int      g_flags[2];

// ---------------- bf16 split helpers ----------------
// hi = truncate x to bf16 (top 16 bits); lo = rn-bf16(x - hi).
__device__ __forceinline__ void split2_bf16(float x0, float x1,
                                            uint32_t& whi, uint32_t& wlo) {
    uint32_t b0 = __float_as_uint(x0), b1 = __float_as_uint(x1);
    whi = __byte_perm(b0, b1, 0x7632);             // {hi(x1), hi(x0)}
    float h0 = __uint_as_float(b0 & 0xFFFF0000u);
    float h1 = __uint_as_float(b1 & 0xFFFF0000u);
    float l0 = x0 - h0, l1 = x1 - h1;
    asm("cvt.rn.bf16x2.f32 %0, %1, %2;" : "=r"(wlo) : "f"(l1), "f"(l0));
}

__device__ __forceinline__ void mma16(float* c, const uint32_t* a, const uint32_t* b) {
    asm volatile(
        "mma.sync.aligned.m16n8k16.row.col.f32.bf16.bf16.f32 "
        "{%0,%1,%2,%3}, {%4,%5,%6,%7}, {%8,%9}, {%0,%1,%2,%3};"
        : "+f"(c[0]), "+f"(c[1]), "+f"(c[2]), "+f"(c[3])
        : "r"(a[0]), "r"(a[1]), "r"(a[2]), "r"(a[3]), "r"(b[0]), "r"(b[1]));
}

// ---------------- index dtype ----------------
__device__ __forceinline__ long long fetch_idx(const void* p, long long i, int is32) {
    if (is32) return (long long)((const int*)p)[i];
    return ((const long long*)p)[i];
}

__global__ void k_zero() {
    int i = blockIdx.x * blockDim.x + threadIdx.x;
    if (i < NN) g_degi[i] = 0;
    if (i < GG * DD) g_pool[i] = 0.f;
    if (i < GG) g_cnt[i] = 0.f;
    if (i < 2) g_flags[i] = 0;
}

__global__ void k_detect2(const unsigned* __restrict__ ei, long long ei_words,
                          const unsigned* __restrict__ bt, long long bt_words) {
    long long i = 2ll * ((long long)blockIdx.x * blockDim.x + threadIdx.x) + 1;
    unsigned v0 = (i < ei_words) ? ei[i] : 0u;
    unsigned v1 = (i < bt_words) ? bt[i] : 0u;
#pragma unroll
    for (int o = 16; o > 0; o >>= 1) {
        v0 |= __shfl_xor_sync(0xffffffffu, v0, o);
        v1 |= __shfl_xor_sync(0xffffffffu, v1, o);
    }
    if ((threadIdx.x & 31) == 0) {
        if (v0) atomicOr(&g_flags[0], 1);
        if (v1) atomicOr(&g_flags[1], 1);
    }
}

// pack all three weight matrices once: WpH/WpL[k'][n] = bf16 pair (W[2k'][n], W[2k'+1][n])
__global__ void k_prepw(const float* __restrict__ W1, const float* __restrict__ W2,
                        const float* __restrict__ W3) {
    int idx = blockIdx.x * 256 + threadIdx.x;   // k'(128) x n(256)
    if (idx >= 128 * DD) return;
    int kp = idx >> 8, n = idx & 255;
    const float* Ws[3] = {W1, W2, W3};
#pragma unroll
    for (int l = 0; l < 3; l++) {
        float x0 = Ws[l][(2 * kp) * DD + n];
        float x1 = Ws[l][(2 * kp + 1) * DD + n];
        uint32_t h, lo;
        split2_bf16(x0, x1, h, lo);
        g_WpH[l][kp * DD + n] = h;
        g_WpL[l][kp * DD + n] = lo;
    }
}

__global__ void k_count(const void* __restrict__ ei, long long E) {
    long long e = (long long)blockIdx.x * blockDim.x + threadIdx.x;
    if (e >= E) return;
    int is32 = g_flags[0];
    long long d = fetch_idx(ei, E + e, is32);
    atomicAdd(&g_degi[d], 1);
}

__global__ void k_scan_dinv() {
    __shared__ int part[1024];
    const int CH = (NN + 1023) / 1024;
    int t = threadIdx.x;
    int beg = t * CH, end = min(beg + CH, NN);
    int s = 0;
    for (int i = beg; i < end; i++) {
        int d = g_degi[i];
        g_dinv[i] = rsqrtf((float)d + 1.0f);
        s += d;
    }
    part[t] = s;
    __syncthreads();
    for (int off = 1; off < 1024; off <<= 1) {
        int v = (t >= off) ? part[t - off] : 0;
        __syncthreads();
        part[t] += v;
        __syncthreads();
    }
    int excl = (t == 0) ? 0 : part[t - 1];
    for (int i = beg; i < end; i++) {
        g_rowptr[i] = excl;
        g_cursor[i] = excl;
        excl += g_degi[i];
    }
    if (t == 1023) g_rowptr[NN] = part[1023];
}

__global__ void k_fill(const void* __restrict__ ei, long long E) {
    long long e = (long long)blockIdx.x * blockDim.x + threadIdx.x;
    if (e >= E) return;
    int is32 = g_flags[0];
    int s = (int)fetch_idx(ei, e, is32);
    int d = (int)fetch_idx(ei, E + e, is32);
    int pos = atomicAdd(&g_cursor[d], 1);
    g_csr_src[pos] = s;
    g_csr_w[pos] = g_dinv[s] * g_dinv[d];
}

// ---------------- bf16x2-split tensor GEMM: C[M,256] = A[M,256] @ W ------------
// Block tile 128x128 (grid 391 x 2), 8 warps (2m x 4n), warp tile 64x32,
// K stepped by 16 (one packed-word column of 8), double-buffered smem.
// acc += ah*bh + ah*bl + al*bh  (al*bl ~2^-16, dropped)
#define APAD 12    // (12g+t)%32 distinct across a warp
#define BPAD 136   // 136%32==8 -> (8t+g)%32 distinct
#define A_WORDS (2 * 2 * 128 * APAD)           // 6144
#define B_WORDS (2 * 2 * 8 * BPAD)             // 4352
#define GEMM_SMEM ((A_WORDS + B_WORDS) * 4)    // 41984 bytes

#define AS(b, h, r, k) sA[((((b) * 2 + (h)) * 128 + (r)) * APAD) + (k)]
#define BS(b, h, k, n) sB[((((b) * 2 + (h)) * 8 + (k)) * BPAD) + (n)]

__global__ __launch_bounds__(256, 2) void k_gemm6(const float* __restrict__ A,
                                                  const uint32_t* __restrict__ BH,
                                                  const uint32_t* __restrict__ BL,
                                                  float* __restrict__ C, int M) {
    extern __shared__ uint32_t smem_dyn[];
    uint32_t* sA = smem_dyn;
    uint32_t* sB = smem_dyn + A_WORDS;

    int tid = threadIdx.x, wid = tid >> 5, lane = tid & 31;
    int g = lane >> 2, t = lane & 3;
    int wm = wid & 1, wn = wid >> 1;       // 2(m) x 4(n); warp tile 64x32
    int bm = blockIdx.x * 128;
    int bn = blockIdx.y * 128;

    // staging mapping
    int a_row  = tid >> 1;                 // 0..127
    int a_half = tid & 1;                  // k 0-7 or 8-15 of the 16-chunk
    int b_kp   = tid >> 5;                 // packed-k row 0..7
    int b_col  = (tid & 31) * 4;           // 4 n-words

    long long a_base = (long long)(bm + a_row) * DD + a_half * 8;
    bool a_ok = (bm + a_row) < M;
    const float4 z4 = make_float4(0.f, 0.f, 0.f, 0.f);

    float acc[4][4][4];
#pragma unroll
    for (int i = 0; i < 4; i++)
#pragma unroll
        for (int j = 0; j < 4; j++)
#pragma unroll
            for (int q = 0; q < 4; q++) acc[i][j][q] = 0.f;

    // helper lambda-ish staging via macro-free code:
    // prologue: stage chunk 0 into buffer 0
    {
        float4 v0 = a_ok ? *(const float4*)(A + a_base)     : z4;
        float4 v1 = a_ok ? *(const float4*)(A + a_base + 4) : z4;
        uint4 h, l;
        split2_bf16(v0.x, v0.y, h.x, l.x);
        split2_bf16(v0.z, v0.w, h.y, l.y);
        split2_bf16(v1.x, v1.y, h.z, l.z);
        split2_bf16(v1.z, v1.w, h.w, l.w);
        *(uint4*)&AS(0, 0, a_row, a_half * 4) = h;
        *(uint4*)&AS(0, 1, a_row, a_half * 4) = l;
        uint4 bh4 = *(const uint4*)(BH + (long long)b_kp * DD + bn + b_col);
        uint4 bl4 = *(const uint4*)(BL + (long long)b_kp * DD + bn + b_col);
        *(uint4*)&BS(0, 0, b_kp, b_col) = bh4;
        *(uint4*)&BS(0, 1, b_kp, b_col) = bl4;
    }
    __syncthreads();

    const int NSTEP = DD / 16;   // 16
    for (int k0 = 0; k0 < NSTEP; k0++) {
        int cur = k0 & 1, nxt = cur ^ 1;
        bool more = (k0 + 1) < NSTEP;

        float4 v0 = z4, v1 = z4;
        uint4 pbh = {0, 0, 0, 0}, pbl = {0, 0, 0, 0};
        if (more) {
            int kb = (k0 + 1) * 16;
            v0 = a_ok ? *(const float4*)(A + a_base + kb)     : z4;
            v1 = a_ok ? *(const float4*)(A + a_base + kb + 4) : z4;
            int kp = (k0 + 1) * 8 + b_kp;
            pbh = *(const uint4*)(BH + (long long)kp * DD + bn + b_col);
            pbl = *(const uint4*)(BL + (long long)kp * DD + bn + b_col);
        }

        uint32_t bh[4][2], bl[4][2];
#pragma unroll
        for (int j = 0; j < 4; j++) {
            int n = wn * 32 + 8 * j + g;
            bh[j][0] = BS(cur, 0, t, n);     bh[j][1] = BS(cur, 0, t + 4, n);
            bl[j][0] = BS(cur, 1, t, n);     bl[j][1] = BS(cur, 1, t + 4, n);
        }
#pragma unroll
        for (int i = 0; i < 4; i++) {
            int r = wm * 64 + i * 16;
            uint32_t ah[4], al[4];
            ah[0] = AS(cur, 0, r + g, t);      ah[1] = AS(cur, 0, r + g + 8, t);
            ah[2] = AS(cur, 0, r + g, t + 4);  ah[3] = AS(cur, 0, r + g + 8, t + 4);
            al[0] = AS(cur, 1, r + g, t);      al[1] = AS(cur, 1, r + g + 8, t);
            al[2] = AS(cur, 1, r + g, t + 4);  al[3] = AS(cur, 1, r + g + 8, t + 4);
#pragma unroll
            for (int j = 0; j < 4; j++) {
                mma16(acc[i][j], ah, bh[j]);
                mma16(acc[i][j], ah, bl[j]);
                mma16(acc[i][j], al, bh[j]);
            }
        }

        if (more) {
            uint4 h, l;
            split2_bf16(v0.x, v0.y, h.x, l.x);
            split2_bf16(v0.z, v0.w, h.y, l.y);
            split2_bf16(v1.x, v1.y, h.z, l.z);
            split2_bf16(v1.z, v1.w, h.w, l.w);
            *(uint4*)&AS(nxt, 0, a_row, a_half * 4) = h;
            *(uint4*)&AS(nxt, 1, a_row, a_half * 4) = l;
            *(uint4*)&BS(nxt, 0, b_kp, b_col) = pbh;
            *(uint4*)&BS(nxt, 1, b_kp, b_col) = pbl;
        }
        __syncthreads();
    }

#pragma unroll
    for (int i = 0; i < 4; i++)
#pragma unroll
        for (int j = 0; j < 4; j++) {
            int row0 = bm + wm * 64 + i * 16 + g;
            int col  = bn + wn * 32 + 8 * j + 2 * t;
            if (row0 < M) {
                float2 v = {acc[i][j][0], acc[i][j][1]};
                *(float2*)(C + (long long)row0 * DD + col) = v;
            }
            int row1 = row0 + 8;
            if (row1 < M) {
                float2 v = {acc[i][j][2], acc[i][j][3]};
                *(float2*)(C + (long long)row1 * DD + col) = v;
            }
        }
}

// ---------------- fused aggregate: self-loop + CSR gather + bias + relu --------
__global__ __launch_bounds__(256) void k_aggregate(const float* __restrict__ tmp,
                                                   float* __restrict__ out,
                                                   const float* __restrict__ bias) {
    int node = (int)(((long long)blockIdx.x * blockDim.x + threadIdx.x) >> 5);
    int lane = threadIdx.x & 31;
    if (node >= NN) return;

    float di = g_dinv[node];
    float ws = di * di;
    const float4* r = (const float4*)(tmp + (long long)node * DD);
    float4 v0 = r[lane], v1 = r[lane + 32];
    float4 a0 = {v0.x * ws, v0.y * ws, v0.z * ws, v0.w * ws};
    float4 a1 = {v1.x * ws, v1.y * ws, v1.z * ws, v1.w * ws};

    int p = g_rowptr[node], pe = g_rowptr[node + 1];
    for (; p + 2 <= pe; p += 2) {
        int s0 = g_csr_src[p], s1 = g_csr_src[p + 1];
        float w0 = g_csr_w[p], w1 = g_csr_w[p + 1];
        const float4* r0 = (const float4*)(tmp + (long long)s0 * DD);
        const float4* r1 = (const float4*)(tmp + (long long)s1 * DD);
        float4 u00 = r0[lane], u01 = r0[lane + 32];
        float4 u10 = r1[lane], u11 = r1[lane + 32];
        a0.x += w0 * u00.x; a0.y += w0 * u00.y; a0.z += w0 * u00.z; a0.w += w0 * u00.w;
        a1.x += w0 * u01.x; a1.y += w0 * u01.y; a1.z += w0 * u01.z; a1.w += w0 * u01.w;
        a0.x += w1 * u10.x; a0.y += w1 * u10.y; a0.z += w1 * u10.z; a0.w += w1 * u10.w;
        a1.x += w1 * u11.x; a1.y += w1 * u11.y; a1.z += w1 * u11.z; a1.w += w1 * u11.w;
    }
    if (p < pe) {
        int s = g_csr_src[p];
        float w = g_csr_w[p];
        const float4* rs = (const float4*)(tmp + (long long)s * DD);
        float4 u0 = rs[lane], u1 = rs[lane + 32];
        a0.x += w * u0.x; a0.y += w * u0.y; a0.z += w * u0.z; a0.w += w * u0.w;
        a1.x += w * u1.x; a1.y += w * u1.y; a1.z += w * u1.z; a1.w += w * u1.w;
    }

    float4 b0 = ((const float4*)bias)[lane];
    float4 b1 = ((const float4*)bias)[lane + 32];
    a0.x = fmaxf(a0.x + b0.x, 0.f); a0.y = fmaxf(a0.y + b0.y, 0.f);
    a0.z = fmaxf(a0.z + b0.z, 0.f); a0.w = fmaxf(a0.w + b0.w, 0.f);
    a1.x = fmaxf(a1.x + b1.x, 0.f); a1.y = fmaxf(a1.y + b1.y, 0.f);
    a1.z = fmaxf(a1.z + b1.z, 0.f); a1.w = fmaxf(a1.w + b1.w, 0.f);

    float4* o = (float4*)(out + (long long)node * DD);
    o[lane] = a0;
    o[lane + 32] = a1;
}

// ---------------- pool (batch sorted) + fc ----------------
__global__ void k_pool2(const float* __restrict__ h, const void* __restrict__ batch) {
    int col = threadIdx.x;
    int n0 = blockIdx.x * 128;
    int n1 = min(n0 + 128, NN);
    int is32 = g_flags[1];
    int cur = (int)fetch_idx(batch, n0, is32);
    float acc = 0.f;
    int cnt = 0;
    for (int n = n0; n < n1; n++) {
        int gid = (int)fetch_idx(batch, n, is32);
        if (gid != cur) {
            atomicAdd(&g_pool[cur * DD + col], acc);
            if (col == 0) atomicAdd(&g_cnt[cur], (float)cnt);
            acc = 0.f; cnt = 0; cur = gid;
        }
        acc += h[(long long)n * DD + col];
        cnt++;
    }
    atomicAdd(&g_pool[cur * DD + col], acc);
    if (col == 0) atomicAdd(&g_cnt[cur], (float)cnt);
}

__global__ void k_fc(const float* __restrict__ Wfc, const float* __restrict__ bfc,
                     float* __restrict__ out) {
    int tt = blockIdx.x * blockDim.x + threadIdx.x;
    if (tt >= GG * DOUT) return;
    int g = tt >> 4, o = tt & 15;
    float inv = 1.0f / fmaxf(g_cnt[g], 1.0f);
    float acc = 0.f;
#pragma unroll 8
    for (int k = 0; k < DD; k++) acc += g_pool[g * DD + k] * Wfc[k * DOUT + o];
    out[tt] = acc * inv + bfc[o];
}

// ---------------- launch ----------------
extern "C" void kernel_launch(void* const* d_in, const int* in_sizes, int n_in,
                              void* d_out, int out_size) {
    const float* x     = (const float*)d_in[0];
    const void*  ei    = d_in[1];
    const void*  batch = d_in[2];
    const float* W1 = (const float*)d_in[3];  const float* b1 = (const float*)d_in[4];
    const float* W2 = (const float*)d_in[5];  const float* b2 = (const float*)d_in[6];
    const float* W3 = (const float*)d_in[7];  const float* b3 = (const float*)d_in[8];
    const float* Wfc = (const float*)d_in[9]; const float* bfc = (const float*)d_in[10];
    float* out = (float*)d_out;

    long long E = in_sizes[1] / 2;

    float *S0, *S1;
    uint32_t *WpH, *WpL;
    cudaGetSymbolAddress((void**)&S0, g_S0);
    cudaGetSymbolAddress((void**)&S1, g_S1);
    cudaGetSymbolAddress((void**)&WpH, g_WpH);
    cudaGetSymbolAddress((void**)&WpL, g_WpL);

    cudaFuncSetAttribute(k_gemm6, cudaFuncAttributeMaxDynamicSharedMemorySize,
                         GEMM_SMEM);

    dim3 gemm_grid((NN + 127) / 128, 2);
    const float* bs[3] = {b1, b2, b3};

    // launch order: GEMM is launch #4 -> gets the ncu -s window
    k_zero<<<(NN + 255) / 256, 256>>>();                                       // 1
    k_detect2<<<(int)((in_sizes[1] / 2 + 255) / 256), 256>>>(
        (const unsigned*)ei, (long long)in_sizes[1],
        (const unsigned*)batch, (long long)in_sizes[2]);                       // 2
    k_prepw<<<128 * DD / 256, 256>>>(W1, W2, W3);                              // 3
    k_gemm6<<<gemm_grid, 256, GEMM_SMEM>>>(x, WpH, WpL, S0, NN);               // 4 (profiled)
    k_count<<<(int)((E + 255) / 256), 256>>>(ei, E);                           // 5
    k_scan_dinv<<<1, 1024>>>();                                                // 6
    k_fill<<<(int)((E + 255) / 256), 256>>>(ei, E);                            // 7
    k_aggregate<<<(NN * 32 + 255) / 256, 256>>>(S0, S1, bs[0]);                // 8

    const float* in = S1;
    for (int l = 1; l < 3; l++) {
        k_gemm6<<<gemm_grid, 256, GEMM_SMEM>>>(in, WpH + (size_t)l * 128 * DD,
                                               WpL + (size_t)l * 128 * DD, S0, NN);
        k_aggregate<<<(NN * 32 + 255) / 256, 256>>>(S0, S1, bs[l]);
        in = S1;
    }

    k_pool2<<<(NN + 127) / 128, 256>>>(S1, batch);
    k_fc<<<(GG * DOUT + 255) / 256, 256>>>(Wfc, bfc, out);
}